// round 1
// baseline (speedup 1.0000x reference)
#include <cuda_runtime.h>
#include <math.h>

#define NN 16384
#define EE 262144
#define ET (EE + NN)      // 278528
#define FF 256
#define FEE 128
#define HH 8
#define FIN_NODE 768
#define FIN_EDGE 64

// ---------------- scratch (device globals; no allocations) ----------------
__device__ float g_x[NN * FF];
__device__ float g_xl[NN * FF];
__device__ float g_xr[NN * FF];
__device__ float g_h[NN * FF];
__device__ float g_y[NN * FF];
__device__ float g_hidden[NN * 2 * FF];
__device__ float g_out[NN * FF];
__device__ float g_ea[ET * FEE];          // projected edge attrs incl. self loops
__device__ float g_eemb[(size_t)ET * FF]; // per-layer edge embeddings
__device__ float g_logit[ET * HH];
__device__ float g_expv[ET * HH];
__device__ unsigned g_max[NN * HH];
__device__ float g_sum[NN * HH];
__device__ float g_loopsum[NN * FEE];
__device__ float g_cnt[NN];

// ---------------- helpers ----------------
__device__ __forceinline__ unsigned fkey(float f) {
    unsigned u = __float_as_uint(f);
    return (u & 0x80000000u) ? ~u : (u | 0x80000000u);
}
__device__ __forceinline__ float finv(unsigned u) {
    return (u & 0x80000000u) ? __uint_as_float(u & 0x7fffffffu) : __uint_as_float(~u);
}

__global__ void fillf(float* p, float v, int n) {
    int i = blockIdx.x * blockDim.x + threadIdx.x;
    if (i < n) p[i] = v;
}

// ---------------- generic tiled GEMM: C[M,Nc] = A[M,K] @ B[Nc,K]^T (+epi) ----
// EPI: 0 = none, 1 = +bias[col], 2 = exact gelu
template <int EPI>
__global__ void gemm_nt(const float* __restrict__ A, const float* __restrict__ B,
                        const float* __restrict__ bias, float* __restrict__ C,
                        int M, int Nc, int K) {
    __shared__ float As[16][68];
    __shared__ float Bs[16][68];
    const int tx = threadIdx.x, ty = threadIdx.y;           // 16 x 16
    const int rowBase = blockIdx.y * 64, colBase = blockIdx.x * 64;
    const int t = ty * 16 + tx;
    const int lr = t >> 2, lc4 = t & 3;                     // load row / float4 col

    float acc[4][4] = {};
    for (int k0 = 0; k0 < K; k0 += 16) {
        float4 av = *(const float4*)&A[(size_t)(rowBase + lr) * K + k0 + lc4 * 4];
        float4 bv = *(const float4*)&B[(size_t)(colBase + lr) * K + k0 + lc4 * 4];
        __syncthreads();
        As[lc4 * 4 + 0][lr] = av.x; As[lc4 * 4 + 1][lr] = av.y;
        As[lc4 * 4 + 2][lr] = av.z; As[lc4 * 4 + 3][lr] = av.w;
        Bs[lc4 * 4 + 0][lr] = bv.x; Bs[lc4 * 4 + 1][lr] = bv.y;
        Bs[lc4 * 4 + 2][lr] = bv.z; Bs[lc4 * 4 + 3][lr] = bv.w;
        __syncthreads();
#pragma unroll
        for (int kk = 0; kk < 16; kk++) {
            float4 a = *(const float4*)&As[kk][ty * 4];
            float4 b = *(const float4*)&Bs[kk][tx * 4];
            acc[0][0] += a.x * b.x; acc[0][1] += a.x * b.y; acc[0][2] += a.x * b.z; acc[0][3] += a.x * b.w;
            acc[1][0] += a.y * b.x; acc[1][1] += a.y * b.y; acc[1][2] += a.y * b.z; acc[1][3] += a.y * b.w;
            acc[2][0] += a.z * b.x; acc[2][1] += a.z * b.y; acc[2][2] += a.z * b.z; acc[2][3] += a.z * b.w;
            acc[3][0] += a.w * b.x; acc[3][1] += a.w * b.y; acc[3][2] += a.w * b.z; acc[3][3] += a.w * b.w;
        }
    }
#pragma unroll
    for (int i = 0; i < 4; i++) {
#pragma unroll
        for (int j = 0; j < 4; j++) {
            int r = rowBase + ty * 4 + i, c = colBase + tx * 4 + j;
            float v = acc[i][j];
            if (EPI == 1) v += bias[c];
            if (EPI == 2) v = 0.5f * v * (1.0f + erff(v * 0.70710678118654752f));
            C[(size_t)r * Nc + c] = v;
        }
    }
}

// ---------------- self-loop attr (mean of incoming projected edge attrs) ----
__global__ void loop_accum(const int* __restrict__ ei) {
    int i = blockIdx.x * blockDim.x + threadIdx.x;
    if (i >= EE * FEE) return;
    int e = i >> 7, c = i & 127;
    int dst = ei[EE + e];
    atomicAdd(&g_loopsum[dst * FEE + c], g_ea[(size_t)e * FEE + c]);
    if (c == 0) atomicAdd(&g_cnt[dst], 1.0f);
}

__global__ void loop_fin() {
    int i = blockIdx.x * blockDim.x + threadIdx.x;
    if (i >= NN * FEE) return;
    int n = i >> 7, c = i & 127;
    g_ea[(size_t)(EE + n) * FEE + c] = g_loopsum[i] / fmaxf(g_cnt[n], 1.0f);
}

// ---------------- edge logits + segment max (warp per edge) ----------------
__global__ void edge_logits_k(const int* __restrict__ ei, const float* __restrict__ att) {
    int w = (blockIdx.x * blockDim.x + threadIdx.x) >> 5;
    int lane = threadIdx.x & 31;
    if (w >= ET) return;
    int src, dst;
    if (w < EE) { src = ei[w]; dst = ei[EE + w]; } else { src = w - EE; dst = src; }
    const float* xl = &g_xl[(size_t)src * FF];
    const float* xr = &g_xr[(size_t)dst * FF];
    const float* em = &g_eemb[(size_t)w * FF];
#pragma unroll
    for (int j = 0; j < HH; j++) {
        int c = j * 32 + lane;
        float m = xl[c] + xr[c] + em[c];
        m = m >= 0.0f ? m : 0.2f * m;
        float v = m * att[c];
        v += __shfl_xor_sync(0xffffffffu, v, 16);
        v += __shfl_xor_sync(0xffffffffu, v, 8);
        v += __shfl_xor_sync(0xffffffffu, v, 4);
        v += __shfl_xor_sync(0xffffffffu, v, 2);
        v += __shfl_xor_sync(0xffffffffu, v, 1);
        if (lane == 0) {
            g_logit[w * HH + j] = v;
            atomicMax(&g_max[dst * HH + j], fkey(v));
        }
    }
}

// ---------------- exp + segment sum ----------------
__global__ void edge_expsum_k(const int* __restrict__ ei) {
    int i = blockIdx.x * blockDim.x + threadIdx.x;
    if (i >= ET * HH) return;
    int e = i >> 3, h = i & 7;
    int dst = (e < EE) ? ei[EE + e] : e - EE;
    float mx = finv(g_max[dst * HH + h]);
    float ex = expf(g_logit[i] - mx);
    g_expv[i] = ex;
    atomicAdd(&g_sum[dst * HH + h], ex);
}

// ---------------- weighted aggregation (warp per edge) ----------------
__global__ void edge_aggregate_k(const int* __restrict__ ei) {
    int w = (blockIdx.x * blockDim.x + threadIdx.x) >> 5;
    int lane = threadIdx.x & 31;
    if (w >= ET) return;
    int src, dst;
    if (w < EE) { src = ei[w]; dst = ei[EE + w]; } else { src = w - EE; dst = src; }
    const float* xl = &g_xl[(size_t)src * FF];
    float* op = &g_out[(size_t)dst * FF];
#pragma unroll
    for (int j = 0; j < HH; j++) {
        float a = g_expv[w * HH + j] / (g_sum[dst * HH + j] + 1e-16f);
        int c = j * 32 + lane;
        atomicAdd(&op[c], a * xl[c]);
    }
}

// ---------------- residual + (opt bias) + LayerNorm ----------------
__global__ void ln_k(const float* __restrict__ a, const float* __restrict__ b,
                     const float* __restrict__ cb, const float* __restrict__ g,
                     const float* __restrict__ beta, float* __restrict__ o) {
    int n = blockIdx.x, c = threadIdx.x; // 256 threads
    float v = a[(size_t)n * FF + c] + b[(size_t)n * FF + c] + (cb ? cb[c] : 0.0f);
    float s = v, q = v * v;
#pragma unroll
    for (int off = 16; off; off >>= 1) {
        s += __shfl_xor_sync(0xffffffffu, s, off);
        q += __shfl_xor_sync(0xffffffffu, q, off);
    }
    __shared__ float ss[8], sq[8];
    if ((c & 31) == 0) { ss[c >> 5] = s; sq[c >> 5] = q; }
    __syncthreads();
    float S = 0.0f, Q = 0.0f;
#pragma unroll
    for (int i = 0; i < 8; i++) { S += ss[i]; Q += sq[i]; }
    float mu = S * (1.0f / FF);
    float var = Q * (1.0f / FF) - mu * mu;
    o[(size_t)n * FF + c] = (v - mu) * rsqrtf(var + 1e-5f) * g[c] + beta[c];
}

// ---------------- host ----------------
static float* symf(const void* sym) {
    void* p = nullptr;
    cudaGetSymbolAddress(&p, sym);
    return (float*)p;
}

extern "C" void kernel_launch(void* const* d_in, const int* in_sizes, int n_in,
                              void* d_out, int out_size) {
    const float* node_feats  = (const float*)d_in[0];
    const int*   edge_index  = (const int*)d_in[1];
    const float* edge_attr   = (const float*)d_in[2];
    const float* init_node_w = (const float*)d_in[3];
    const float* init_edge_w = (const float*)d_in[4];
    const float* lin_l_w     = (const float*)d_in[5];
    const float* lin_l_b     = (const float*)d_in[6];
    const float* lin_r_w     = (const float*)d_in[7];
    const float* lin_r_b     = (const float*)d_in[8];
    const float* lin_edge_w  = (const float*)d_in[9];
    const float* att         = (const float*)d_in[10];
    const float* gat_bias    = (const float*)d_in[11];
    const float* ln1_g       = (const float*)d_in[12];
    const float* ln1_b       = (const float*)d_in[13];
    const float* mlp_w1      = (const float*)d_in[14];
    const float* mlp_w2      = (const float*)d_in[15];
    const float* ln2_g       = (const float*)d_in[16];
    const float* ln2_b       = (const float*)d_in[17];

    float* px   = symf(g_x);
    float* pxl  = symf(g_xl);
    float* pxr  = symf(g_xr);
    float* ph   = symf(g_h);
    float* py   = symf(g_y);
    float* phid = symf(g_hidden);
    float* pout = symf(g_out);
    float* pea  = symf(g_ea);
    float* pemb = symf(g_eemb);
    float* pmax = symf(g_max);
    float* psum = symf(g_sum);
    float* plps = symf(g_loopsum);
    float* pcnt = symf(g_cnt);

    dim3 tb(16, 16);

    // x = node_feats @ init_node_w^T          [NN, FF]
    gemm_nt<0><<<dim3(FF / 64, NN / 64), tb>>>(node_feats, init_node_w, nullptr, px, NN, FF, FIN_NODE);
    // ea(first EE rows) = edge_attr @ init_edge_w^T   [EE, FEE]
    gemm_nt<0><<<dim3(FEE / 64, EE / 64), tb>>>(edge_attr, init_edge_w, nullptr, pea, EE, FEE, FIN_EDGE);

    // self-loop attrs = per-dst mean of incoming ea
    fillf<<<(NN * FEE + 255) / 256, 256>>>(plps, 0.0f, NN * FEE);
    fillf<<<(NN + 255) / 256, 256>>>(pcnt, 0.0f, NN);
    loop_accum<<<(EE * FEE + 255) / 256, 256>>>(edge_index);
    loop_fin<<<(NN * FEE + 255) / 256, 256>>>();

    for (int l = 0; l < 2; l++) {
        fillf<<<(NN * HH + 255) / 256, 256>>>(pmax, 0.0f, NN * HH);  // fkey(-inf) sentinel = 0
        fillf<<<(NN * HH + 255) / 256, 256>>>(psum, 0.0f, NN * HH);
        fillf<<<(NN * FF + 255) / 256, 256>>>(pout, 0.0f, NN * FF);

        gemm_nt<1><<<dim3(FF / 64, NN / 64), tb>>>(px, lin_l_w + (size_t)l * FF * FF,
                                                   lin_l_b + l * FF, pxl, NN, FF, FF);
        gemm_nt<1><<<dim3(FF / 64, NN / 64), tb>>>(px, lin_r_w + (size_t)l * FF * FF,
                                                   lin_r_b + l * FF, pxr, NN, FF, FF);
        gemm_nt<0><<<dim3(FF / 64, ET / 64), tb>>>(pea, lin_edge_w + (size_t)l * FF * FEE,
                                                   nullptr, pemb, ET, FF, FEE);

        edge_logits_k<<<(ET * 32 + 255) / 256, 256>>>(edge_index, att + l * FF);
        edge_expsum_k<<<(ET * HH + 255) / 256, 256>>>(edge_index);
        edge_aggregate_k<<<(ET * 32 + 255) / 256, 256>>>(edge_index);

        // h = LN(x + out + gat_bias)
        ln_k<<<NN, FF>>>(px, pout, gat_bias + l * FF, ln1_g + l * FF, ln1_b + l * FF, ph);
        // hidden = gelu(h @ W1^T)   [NN, 512]
        gemm_nt<2><<<dim3(512 / 64, NN / 64), tb>>>(ph, mlp_w1 + (size_t)l * 512 * FF,
                                                    nullptr, phid, NN, 512, FF);
        // y = hidden @ W2^T         [NN, 256]
        gemm_nt<0><<<dim3(FF / 64, NN / 64), tb>>>(phid, mlp_w2 + (size_t)l * FF * 512,
                                                   nullptr, py, NN, FF, 512);
        // x = LN(h + y)   (last layer writes straight to d_out)
        float* xo = (l == 1) ? (float*)d_out : px;
        ln_k<<<NN, FF>>>(ph, py, nullptr, ln2_g + l * FF, ln2_b + l * FF, xo);
    }
}

// round 2
// speedup vs baseline: 1.6489x; 1.6489x over previous
#include <cuda_runtime.h>
#include <cuda_bf16.h>
#include <math.h>

#define NN 16384
#define EE 262144
#define ET (EE + NN)      // 278528
#define FF 256
#define FEE 128
#define HH 8
#define FIN_NODE 768
#define FIN_EDGE 64

// ---------------- scratch (device globals; no allocations) ----------------
__device__ float g_x[NN * FF];
__device__ float g_xl[NN * FF];
__device__ float g_xr[NN * FF];
__device__ float g_h[NN * FF];
__device__ float g_y[NN * FF];
__device__ float g_hidden[NN * 2 * FF];
__device__ float g_out[NN * FF];
__device__ float g_ea[ET * FEE];          // projected edge attrs incl. self loops
__device__ float g_eemb[(size_t)ET * FF]; // per-layer edge embeddings
__device__ float g_logit[ET * HH];
__device__ float g_expv[ET * HH];
__device__ unsigned g_max[NN * HH];
__device__ float g_sum[NN * HH];
__device__ float g_loopsum[NN * FEE];
__device__ float g_cnt[NN];

// ---------------- helpers ----------------
__device__ __forceinline__ unsigned fkey(float f) {
    unsigned u = __float_as_uint(f);
    return (u & 0x80000000u) ? ~u : (u | 0x80000000u);
}
__device__ __forceinline__ float finv(unsigned u) {
    return (u & 0x80000000u) ? __uint_as_float(u & 0x7fffffffu) : __uint_as_float(~u);
}

__global__ void fillf(float* p, float v, int n) {
    int i = blockIdx.x * blockDim.x + threadIdx.x;
    if (i < n) p[i] = v;
}

// =================== bf16-split tensor-core GEMM ===========================
// C[M,Nc] = A[M,K] @ B[Nc,K]^T  via mma.sync m16n8k16 bf16, 2-term split:
//   x = hi + lo (bf16 each);  a*b ≈ ah*bh + ah*bl + al*bh   (fp32 accumulate)
// Block: 256 thr (8 warps, 4x2), tile 128(M) x 64(N), BK=32.
// EPI: 0 none, 1 +bias[col], 2 exact gelu
#define SKP 40   // padded smem row (bf16 elems): conflict-free frag loads

__device__ __forceinline__ void mma16816(float c[4], const unsigned a[4], const unsigned b[2]) {
    asm volatile(
        "mma.sync.aligned.m16n8k16.row.col.f32.bf16.bf16.f32 "
        "{%0,%1,%2,%3},{%4,%5,%6,%7},{%8,%9},{%0,%1,%2,%3};\n"
        : "+f"(c[0]), "+f"(c[1]), "+f"(c[2]), "+f"(c[3])
        : "r"(a[0]), "r"(a[1]), "r"(a[2]), "r"(a[3]), "r"(b[0]), "r"(b[1]));
}

__device__ __forceinline__ void split4(float4 v, unsigned& h01, unsigned& h23,
                                       unsigned& l01, unsigned& l23) {
    __nv_bfloat16 h0 = __float2bfloat16(v.x), h1 = __float2bfloat16(v.y);
    __nv_bfloat16 h2 = __float2bfloat16(v.z), h3 = __float2bfloat16(v.w);
    __nv_bfloat16 l0 = __float2bfloat16(v.x - __bfloat162float(h0));
    __nv_bfloat16 l1 = __float2bfloat16(v.y - __bfloat162float(h1));
    __nv_bfloat16 l2 = __float2bfloat16(v.z - __bfloat162float(h2));
    __nv_bfloat16 l3 = __float2bfloat16(v.w - __bfloat162float(h3));
    h01 = ((unsigned)__bfloat16_as_ushort(h1) << 16) | __bfloat16_as_ushort(h0);
    h23 = ((unsigned)__bfloat16_as_ushort(h3) << 16) | __bfloat16_as_ushort(h2);
    l01 = ((unsigned)__bfloat16_as_ushort(l1) << 16) | __bfloat16_as_ushort(l0);
    l23 = ((unsigned)__bfloat16_as_ushort(l3) << 16) | __bfloat16_as_ushort(l2);
}

template <int EPI>
__global__ __launch_bounds__(256)
void gemm_nt(const float* __restrict__ A, const float* __restrict__ B,
             const float* __restrict__ bias, float* __restrict__ C,
             int M, int Nc, int K) {
    __shared__ __nv_bfloat16 Ah[128][SKP], Al[128][SKP];
    __shared__ __nv_bfloat16 Bh[64][SKP],  Bl[64][SKP];

    const int tid = threadIdx.x, lane = tid & 31, w = tid >> 5;
    const int wm = w >> 1, wn = w & 1;               // 4 x 2 warp grid
    const int rowBase = blockIdx.y * 128, colBase = blockIdx.x * 64;
    const int g = lane >> 2, tg = lane & 3;

    float c[2][4][4] = {};

    const int lr = tid >> 3;          // 0..31
    const int lc = (tid & 7) * 4;     // 0,4,...,28

    for (int k0 = 0; k0 < K; k0 += 32) {
        // ---- stage global loads into registers (fp32) ----
        float4 av[4], bv[2];
#pragma unroll
        for (int i = 0; i < 4; i++)
            av[i] = *(const float4*)&A[(size_t)(rowBase + lr + i * 32) * K + k0 + lc];
#pragma unroll
        for (int i = 0; i < 2; i++)
            bv[i] = *(const float4*)&B[(size_t)(colBase + lr + i * 32) * K + k0 + lc];

        __syncthreads();
        // ---- split-convert + store to smem ----
#pragma unroll
        for (int i = 0; i < 4; i++) {
            unsigned h01, h23, l01, l23;
            split4(av[i], h01, h23, l01, l23);
            *(uint2*)&Ah[lr + i * 32][lc] = make_uint2(h01, h23);
            *(uint2*)&Al[lr + i * 32][lc] = make_uint2(l01, l23);
        }
#pragma unroll
        for (int i = 0; i < 2; i++) {
            unsigned h01, h23, l01, l23;
            split4(bv[i], h01, h23, l01, l23);
            *(uint2*)&Bh[lr + i * 32][lc] = make_uint2(h01, h23);
            *(uint2*)&Bl[lr + i * 32][lc] = make_uint2(l01, l23);
        }
        __syncthreads();

        // ---- compute: 2 x k16 chunks ----
#pragma unroll
        for (int kk = 0; kk < 2; kk++) {
            unsigned ah[2][4], al[2][4], bh[4][2], bl[4][2];
            const int kf = kk * 16 + tg * 2;
#pragma unroll
            for (int mi = 0; mi < 2; mi++) {
                int m = wm * 32 + mi * 16 + g;
                ah[mi][0] = *(const unsigned*)&Ah[m][kf];
                ah[mi][1] = *(const unsigned*)&Ah[m + 8][kf];
                ah[mi][2] = *(const unsigned*)&Ah[m][kf + 8];
                ah[mi][3] = *(const unsigned*)&Ah[m + 8][kf + 8];
                al[mi][0] = *(const unsigned*)&Al[m][kf];
                al[mi][1] = *(const unsigned*)&Al[m + 8][kf];
                al[mi][2] = *(const unsigned*)&Al[m][kf + 8];
                al[mi][3] = *(const unsigned*)&Al[m + 8][kf + 8];
            }
#pragma unroll
            for (int ni = 0; ni < 4; ni++) {
                int n = wn * 32 + ni * 8 + g;
                bh[ni][0] = *(const unsigned*)&Bh[n][kf];
                bh[ni][1] = *(const unsigned*)&Bh[n][kf + 8];
                bl[ni][0] = *(const unsigned*)&Bl[n][kf];
                bl[ni][1] = *(const unsigned*)&Bl[n][kf + 8];
            }
#pragma unroll
            for (int mi = 0; mi < 2; mi++)
#pragma unroll
                for (int ni = 0; ni < 4; ni++) {
                    mma16816(c[mi][ni], ah[mi], bh[ni]);
                    mma16816(c[mi][ni], ah[mi], bl[ni]);
                    mma16816(c[mi][ni], al[mi], bh[ni]);
                }
        }
    }

    // ---- epilogue ----
#pragma unroll
    for (int mi = 0; mi < 2; mi++)
#pragma unroll
        for (int ni = 0; ni < 4; ni++) {
            int col = colBase + wn * 32 + ni * 8 + tg * 2;
            float b0 = 0.f, b1 = 0.f;
            if (EPI == 1) { b0 = bias[col]; b1 = bias[col + 1]; }
#pragma unroll
            for (int half = 0; half < 2; half++) {
                int row = rowBase + wm * 32 + mi * 16 + g + half * 8;
                float v0 = c[mi][ni][half * 2] + b0;
                float v1 = c[mi][ni][half * 2 + 1] + b1;
                if (EPI == 2) {
                    v0 = 0.5f * v0 * (1.0f + erff(v0 * 0.70710678118654752f));
                    v1 = 0.5f * v1 * (1.0f + erff(v1 * 0.70710678118654752f));
                }
                *(float2*)&C[(size_t)row * Nc + col] = make_float2(v0, v1);
            }
        }
}

// ---------------- self-loop attr (mean of incoming projected edge attrs) ----
__global__ void loop_accum(const int* __restrict__ ei) {
    int i = blockIdx.x * blockDim.x + threadIdx.x;
    if (i >= EE * FEE) return;
    int e = i >> 7, c = i & 127;
    int dst = ei[EE + e];
    atomicAdd(&g_loopsum[dst * FEE + c], g_ea[(size_t)e * FEE + c]);
    if (c == 0) atomicAdd(&g_cnt[dst], 1.0f);
}

__global__ void loop_fin() {
    int i = blockIdx.x * blockDim.x + threadIdx.x;
    if (i >= NN * FEE) return;
    int n = i >> 7, c = i & 127;
    g_ea[(size_t)(EE + n) * FEE + c] = g_loopsum[i] / fmaxf(g_cnt[n], 1.0f);
}

// ---------------- edge logits + segment max (warp per edge) ----------------
__global__ void edge_logits_k(const int* __restrict__ ei, const float* __restrict__ att) {
    int w = (blockIdx.x * blockDim.x + threadIdx.x) >> 5;
    int lane = threadIdx.x & 31;
    if (w >= ET) return;
    int src, dst;
    if (w < EE) { src = ei[w]; dst = ei[EE + w]; } else { src = w - EE; dst = src; }
    const float* xl = &g_xl[(size_t)src * FF];
    const float* xr = &g_xr[(size_t)dst * FF];
    const float* em = &g_eemb[(size_t)w * FF];
#pragma unroll
    for (int j = 0; j < HH; j++) {
        int c = j * 32 + lane;
        float m = xl[c] + xr[c] + em[c];
        m = m >= 0.0f ? m : 0.2f * m;
        float v = m * att[c];
        v += __shfl_xor_sync(0xffffffffu, v, 16);
        v += __shfl_xor_sync(0xffffffffu, v, 8);
        v += __shfl_xor_sync(0xffffffffu, v, 4);
        v += __shfl_xor_sync(0xffffffffu, v, 2);
        v += __shfl_xor_sync(0xffffffffu, v, 1);
        if (lane == 0) {
            g_logit[w * HH + j] = v;
            atomicMax(&g_max[dst * HH + j], fkey(v));
        }
    }
}

// ---------------- exp + segment sum ----------------
__global__ void edge_expsum_k(const int* __restrict__ ei) {
    int i = blockIdx.x * blockDim.x + threadIdx.x;
    if (i >= ET * HH) return;
    int e = i >> 3, h = i & 7;
    int dst = (e < EE) ? ei[EE + e] : e - EE;
    float mx = finv(g_max[dst * HH + h]);
    float ex = expf(g_logit[i] - mx);
    g_expv[i] = ex;
    atomicAdd(&g_sum[dst * HH + h], ex);
}

// ---------------- weighted aggregation (warp per edge) ----------------
__global__ void edge_aggregate_k(const int* __restrict__ ei) {
    int w = (blockIdx.x * blockDim.x + threadIdx.x) >> 5;
    int lane = threadIdx.x & 31;
    if (w >= ET) return;
    int src, dst;
    if (w < EE) { src = ei[w]; dst = ei[EE + w]; } else { src = w - EE; dst = src; }
    const float* xl = &g_xl[(size_t)src * FF];
    float* op = &g_out[(size_t)dst * FF];
#pragma unroll
    for (int j = 0; j < HH; j++) {
        float a = g_expv[w * HH + j] / (g_sum[dst * HH + j] + 1e-16f);
        int c = j * 32 + lane;
        atomicAdd(&op[c], a * xl[c]);
    }
}

// ---------------- residual + (opt bias) + LayerNorm ----------------
__global__ void ln_k(const float* __restrict__ a, const float* __restrict__ b,
                     const float* __restrict__ cb, const float* __restrict__ g,
                     const float* __restrict__ beta, float* __restrict__ o) {
    int n = blockIdx.x, c = threadIdx.x; // 256 threads
    float v = a[(size_t)n * FF + c] + b[(size_t)n * FF + c] + (cb ? cb[c] : 0.0f);
    float s = v, q = v * v;
#pragma unroll
    for (int off = 16; off; off >>= 1) {
        s += __shfl_xor_sync(0xffffffffu, s, off);
        q += __shfl_xor_sync(0xffffffffu, q, off);
    }
    __shared__ float ss[8], sq[8];
    if ((c & 31) == 0) { ss[c >> 5] = s; sq[c >> 5] = q; }
    __syncthreads();
    float S = 0.0f, Q = 0.0f;
#pragma unroll
    for (int i = 0; i < 8; i++) { S += ss[i]; Q += sq[i]; }
    float mu = S * (1.0f / FF);
    float var = Q * (1.0f / FF) - mu * mu;
    o[(size_t)n * FF + c] = (v - mu) * rsqrtf(var + 1e-5f) * g[c] + beta[c];
}

// ---------------- host ----------------
static float* symf(const void* sym) {
    void* p = nullptr;
    cudaGetSymbolAddress(&p, sym);
    return (float*)p;
}

extern "C" void kernel_launch(void* const* d_in, const int* in_sizes, int n_in,
                              void* d_out, int out_size) {
    const float* node_feats  = (const float*)d_in[0];
    const int*   edge_index  = (const int*)d_in[1];
    const float* edge_attr   = (const float*)d_in[2];
    const float* init_node_w = (const float*)d_in[3];
    const float* init_edge_w = (const float*)d_in[4];
    const float* lin_l_w     = (const float*)d_in[5];
    const float* lin_l_b     = (const float*)d_in[6];
    const float* lin_r_w     = (const float*)d_in[7];
    const float* lin_r_b     = (const float*)d_in[8];
    const float* lin_edge_w  = (const float*)d_in[9];
    const float* att         = (const float*)d_in[10];
    const float* gat_bias    = (const float*)d_in[11];
    const float* ln1_g       = (const float*)d_in[12];
    const float* ln1_b       = (const float*)d_in[13];
    const float* mlp_w1      = (const float*)d_in[14];
    const float* mlp_w2      = (const float*)d_in[15];
    const float* ln2_g       = (const float*)d_in[16];
    const float* ln2_b       = (const float*)d_in[17];

    float* px   = symf(g_x);
    float* pxl  = symf(g_xl);
    float* pxr  = symf(g_xr);
    float* ph   = symf(g_h);
    float* py   = symf(g_y);
    float* phid = symf(g_hidden);
    float* pout = symf(g_out);
    float* pea  = symf(g_ea);
    float* pemb = symf(g_eemb);
    float* pmax = symf(g_max);
    float* psum = symf(g_sum);
    float* plps = symf(g_loopsum);
    float* pcnt = symf(g_cnt);

    // x = node_feats @ init_node_w^T          [NN, FF]
    gemm_nt<0><<<dim3(FF / 64, NN / 128), 256>>>(node_feats, init_node_w, nullptr, px, NN, FF, FIN_NODE);
    // ea(first EE rows) = edge_attr @ init_edge_w^T   [EE, FEE]
    gemm_nt<0><<<dim3(FEE / 64, EE / 128), 256>>>(edge_attr, init_edge_w, nullptr, pea, EE, FEE, FIN_EDGE);

    // self-loop attrs = per-dst mean of incoming ea
    fillf<<<(NN * FEE + 255) / 256, 256>>>(plps, 0.0f, NN * FEE);
    fillf<<<(NN + 255) / 256, 256>>>(pcnt, 0.0f, NN);
    loop_accum<<<(EE * FEE + 255) / 256, 256>>>(edge_index);
    loop_fin<<<(NN * FEE + 255) / 256, 256>>>();

    for (int l = 0; l < 2; l++) {
        fillf<<<(NN * HH + 255) / 256, 256>>>((float*)pmax, 0.0f, NN * HH);  // fkey sentinel 0
        fillf<<<(NN * HH + 255) / 256, 256>>>(psum, 0.0f, NN * HH);
        fillf<<<(NN * FF + 255) / 256, 256>>>(pout, 0.0f, NN * FF);

        gemm_nt<1><<<dim3(FF / 64, NN / 128), 256>>>(px, lin_l_w + (size_t)l * FF * FF,
                                                     lin_l_b + l * FF, pxl, NN, FF, FF);
        gemm_nt<1><<<dim3(FF / 64, NN / 128), 256>>>(px, lin_r_w + (size_t)l * FF * FF,
                                                     lin_r_b + l * FF, pxr, NN, FF, FF);
        gemm_nt<0><<<dim3(FF / 64, ET / 128), 256>>>(pea, lin_edge_w + (size_t)l * FF * FEE,
                                                     nullptr, pemb, ET, FF, FEE);

        edge_logits_k<<<(ET * 32 + 255) / 256, 256>>>(edge_index, att + l * FF);
        edge_expsum_k<<<(ET * HH + 255) / 256, 256>>>(edge_index);
        edge_aggregate_k<<<(ET * 32 + 255) / 256, 256>>>(edge_index);

        // h = LN(x + out + gat_bias)
        ln_k<<<NN, FF>>>(px, pout, gat_bias + l * FF, ln1_g + l * FF, ln1_b + l * FF, ph);
        // hidden = gelu(h @ W1^T)   [NN, 512]
        gemm_nt<2><<<dim3(512 / 64, NN / 128), 256>>>(ph, mlp_w1 + (size_t)l * 512 * FF,
                                                      nullptr, phid, NN, 512, FF);
        // y = hidden @ W2^T         [NN, 256]
        gemm_nt<0><<<dim3(FF / 64, NN / 128), 256>>>(phid, mlp_w2 + (size_t)l * FF * 512,
                                                     nullptr, py, NN, FF, 512);
        // x = LN(h + y)   (last layer writes straight to d_out)
        float* xo = (l == 1) ? (float*)d_out : px;
        ln_k<<<NN, FF>>>(ph, py, nullptr, ln2_g + l * FF, ln2_b + l * FF, xo);
    }
}

// round 3
// speedup vs baseline: 2.0328x; 1.2328x over previous
#include <cuda_runtime.h>
#include <cuda_bf16.h>
#include <math.h>

#define NN 16384
#define EE 262144
#define ET (EE + NN)      // 278528
#define FF 256
#define FEE 128
#define HH 8
#define FIN_NODE 768
#define FIN_EDGE 64

// ---------------- scratch (device globals; no allocations) ----------------
__device__ float g_x[NN * FF];
__device__ float g_xl[NN * FF];
__device__ float g_xr[NN * FF];
__device__ float g_h[NN * FF];
__device__ float g_y[NN * FF];
__device__ float g_hidden[NN * 2 * FF];
__device__ float g_ea[ET * FEE];          // projected edge attrs incl. self loops
__device__ float g_logit[ET * HH];
__device__ float g_alpha[ET * HH];
__device__ int   g_cnt_i[NN];             // counters / scatter cursors
__device__ int   g_ptr[NN + 1];
__device__ int   g_csr_eid[ET];
__device__ int   g_csr_src[ET];

__global__ void zeroi(int* p, int n) {
    int i = blockIdx.x * blockDim.x + threadIdx.x;
    if (i < n) p[i] = 0;
}

// =================== bf16-split tensor-core GEMM ===========================
#define SKP 40

__device__ __forceinline__ void mma16816(float c[4], const unsigned a[4], const unsigned b[2]) {
    asm volatile(
        "mma.sync.aligned.m16n8k16.row.col.f32.bf16.bf16.f32 "
        "{%0,%1,%2,%3},{%4,%5,%6,%7},{%8,%9},{%0,%1,%2,%3};\n"
        : "+f"(c[0]), "+f"(c[1]), "+f"(c[2]), "+f"(c[3])
        : "r"(a[0]), "r"(a[1]), "r"(a[2]), "r"(a[3]), "r"(b[0]), "r"(b[1]));
}

__device__ __forceinline__ void split4(float4 v, unsigned& h01, unsigned& h23,
                                       unsigned& l01, unsigned& l23) {
    __nv_bfloat16 h0 = __float2bfloat16(v.x), h1 = __float2bfloat16(v.y);
    __nv_bfloat16 h2 = __float2bfloat16(v.z), h3 = __float2bfloat16(v.w);
    __nv_bfloat16 l0 = __float2bfloat16(v.x - __bfloat162float(h0));
    __nv_bfloat16 l1 = __float2bfloat16(v.y - __bfloat162float(h1));
    __nv_bfloat16 l2 = __float2bfloat16(v.z - __bfloat162float(h2));
    __nv_bfloat16 l3 = __float2bfloat16(v.w - __bfloat162float(h3));
    h01 = ((unsigned)__bfloat16_as_ushort(h1) << 16) | __bfloat16_as_ushort(h0);
    h23 = ((unsigned)__bfloat16_as_ushort(h3) << 16) | __bfloat16_as_ushort(h2);
    l01 = ((unsigned)__bfloat16_as_ushort(l1) << 16) | __bfloat16_as_ushort(l0);
    l23 = ((unsigned)__bfloat16_as_ushort(l3) << 16) | __bfloat16_as_ushort(l2);
}

// Shared mainloop: loads A/B tile, split-converts, runs 3-term MMA. Returns accum in c.
#define GEMM_MAINLOOP(A, B, K)                                                        \
    for (int k0 = 0; k0 < (K); k0 += 32) {                                            \
        float4 av[4], bv[2];                                                          \
        _Pragma("unroll")                                                             \
        for (int i = 0; i < 4; i++)                                                   \
            av[i] = *(const float4*)&(A)[(size_t)(rowBase + lr + i * 32) * (K) + k0 + lc]; \
        _Pragma("unroll")                                                             \
        for (int i = 0; i < 2; i++)                                                   \
            bv[i] = *(const float4*)&(B)[(size_t)(colBase + lr + i * 32) * (K) + k0 + lc]; \
        __syncthreads();                                                              \
        _Pragma("unroll")                                                             \
        for (int i = 0; i < 4; i++) {                                                 \
            unsigned h01, h23, l01, l23;                                              \
            split4(av[i], h01, h23, l01, l23);                                        \
            *(uint2*)&Ah[lr + i * 32][lc] = make_uint2(h01, h23);                     \
            *(uint2*)&Al[lr + i * 32][lc] = make_uint2(l01, l23);                     \
        }                                                                             \
        _Pragma("unroll")                                                             \
        for (int i = 0; i < 2; i++) {                                                 \
            unsigned h01, h23, l01, l23;                                              \
            split4(bv[i], h01, h23, l01, l23);                                        \
            *(uint2*)&Bh[lr + i * 32][lc] = make_uint2(h01, h23);                     \
            *(uint2*)&Bl[lr + i * 32][lc] = make_uint2(l01, l23);                     \
        }                                                                             \
        __syncthreads();                                                              \
        _Pragma("unroll")                                                             \
        for (int kk = 0; kk < 2; kk++) {                                              \
            unsigned ah[2][4], al[2][4], bh[4][2], bl[4][2];                          \
            const int kf = kk * 16 + tg * 2;                                          \
            _Pragma("unroll")                                                         \
            for (int mi = 0; mi < 2; mi++) {                                          \
                int m = wm * 32 + mi * 16 + g;                                        \
                ah[mi][0] = *(const unsigned*)&Ah[m][kf];                             \
                ah[mi][1] = *(const unsigned*)&Ah[m + 8][kf];                         \
                ah[mi][2] = *(const unsigned*)&Ah[m][kf + 8];                         \
                ah[mi][3] = *(const unsigned*)&Ah[m + 8][kf + 8];                     \
                al[mi][0] = *(const unsigned*)&Al[m][kf];                             \
                al[mi][1] = *(const unsigned*)&Al[m + 8][kf];                         \
                al[mi][2] = *(const unsigned*)&Al[m][kf + 8];                         \
                al[mi][3] = *(const unsigned*)&Al[m + 8][kf + 8];                     \
            }                                                                         \
            _Pragma("unroll")                                                         \
            for (int ni = 0; ni < 4; ni++) {                                          \
                int n = wn * 32 + ni * 8 + g;                                         \
                bh[ni][0] = *(const unsigned*)&Bh[n][kf];                             \
                bh[ni][1] = *(const unsigned*)&Bh[n][kf + 8];                         \
                bl[ni][0] = *(const unsigned*)&Bl[n][kf];                             \
                bl[ni][1] = *(const unsigned*)&Bl[n][kf + 8];                         \
            }                                                                         \
            _Pragma("unroll")                                                         \
            for (int mi = 0; mi < 2; mi++)                                            \
                _Pragma("unroll")                                                     \
                for (int ni = 0; ni < 4; ni++) {                                      \
                    mma16816(c[mi][ni], ah[mi], bh[ni]);                              \
                    mma16816(c[mi][ni], ah[mi], bl[ni]);                              \
                    mma16816(c[mi][ni], al[mi], bh[ni]);                              \
                }                                                                     \
        }                                                                             \
    }

// C = A @ B^T (+epi).  EPI: 0 none, 1 +bias, 2 gelu
template <int EPI>
__global__ __launch_bounds__(256)
void gemm_nt(const float* __restrict__ A, const float* __restrict__ B,
             const float* __restrict__ bias, float* __restrict__ C,
             int M, int Nc, int K) {
    __shared__ __nv_bfloat16 Ah[128][SKP], Al[128][SKP];
    __shared__ __nv_bfloat16 Bh[64][SKP],  Bl[64][SKP];
    const int tid = threadIdx.x, lane = tid & 31, w = tid >> 5;
    const int wm = w >> 1, wn = w & 1;
    const int rowBase = blockIdx.y * 128, colBase = blockIdx.x * 64;
    const int g = lane >> 2, tg = lane & 3;
    const int lr = tid >> 3, lc = (tid & 7) * 4;
    float c[2][4][4] = {};
    GEMM_MAINLOOP(A, B, K)
#pragma unroll
    for (int mi = 0; mi < 2; mi++)
#pragma unroll
        for (int ni = 0; ni < 4; ni++) {
            int col = colBase + wn * 32 + ni * 8 + tg * 2;
            float b0 = 0.f, b1 = 0.f;
            if (EPI == 1) { b0 = bias[col]; b1 = bias[col + 1]; }
#pragma unroll
            for (int half = 0; half < 2; half++) {
                int row = rowBase + wm * 32 + mi * 16 + g + half * 8;
                float v0 = c[mi][ni][half * 2] + b0;
                float v1 = c[mi][ni][half * 2 + 1] + b1;
                if (EPI == 2) {
                    v0 = 0.5f * v0 * (1.0f + erff(v0 * 0.70710678118654752f));
                    v1 = 0.5f * v1 * (1.0f + erff(v1 * 0.70710678118654752f));
                }
                *(float2*)&C[(size_t)row * Nc + col] = make_float2(v0, v1);
            }
        }
}

// Fused: eemb = g_ea @ W_edge^T, then logits = sum_c leakyrelu(xl[src]+xr[dst]+eemb)*att
// Writes g_logit[e, h] directly; each warp owns one head -> no atomics, no eemb buffer.
__global__ __launch_bounds__(256)
void gemm_edge_logit(const float* __restrict__ B, const int* __restrict__ ei,
                     const float* __restrict__ att) {
    __shared__ __nv_bfloat16 Ah[128][SKP], Al[128][SKP];
    __shared__ __nv_bfloat16 Bh[64][SKP],  Bl[64][SKP];
    const int tid = threadIdx.x, lane = tid & 31, w = tid >> 5;
    const int wm = w >> 1, wn = w & 1;
    const int rowBase = blockIdx.y * 128, colBase = blockIdx.x * 64;
    const int g = lane >> 2, tg = lane & 3;
    const int lr = tid >> 3, lc = (tid & 7) * 4;
    const float* A = g_ea;
    float c[2][4][4] = {};
    GEMM_MAINLOOP(A, B, FEE)

    // epilogue: fused logit
    const int head = (colBase >> 5) + wn;
    float attv[4][2];
#pragma unroll
    for (int ni = 0; ni < 4; ni++) {
        int col = colBase + wn * 32 + ni * 8 + tg * 2;
        attv[ni][0] = att[col]; attv[ni][1] = att[col + 1];
    }
#pragma unroll
    for (int mi = 0; mi < 2; mi++)
#pragma unroll
        for (int half = 0; half < 2; half++) {
            int r = rowBase + wm * 32 + mi * 16 + g + half * 8;
            int src, dst;
            if (r < EE) { src = __ldg(&ei[r]); dst = __ldg(&ei[EE + r]); }
            else { src = r - EE; dst = src; }
            const float* xl = &g_xl[(size_t)src * FF];
            const float* xr = &g_xr[(size_t)dst * FF];
            float part = 0.0f;
#pragma unroll
            for (int ni = 0; ni < 4; ni++) {
                int col = colBase + wn * 32 + ni * 8 + tg * 2;
                float2 xlv = *(const float2*)&xl[col];
                float2 xrv = *(const float2*)&xr[col];
                float m0 = c[mi][ni][half * 2]     + xlv.x + xrv.x;
                float m1 = c[mi][ni][half * 2 + 1] + xlv.y + xrv.y;
                m0 = m0 >= 0.0f ? m0 : 0.2f * m0;
                m1 = m1 >= 0.0f ? m1 : 0.2f * m1;
                part += m0 * attv[ni][0] + m1 * attv[ni][1];
            }
            part += __shfl_xor_sync(0xffffffffu, part, 1);
            part += __shfl_xor_sync(0xffffffffu, part, 2);
            if (tg == 0) g_logit[r * HH + head] = part;
        }
}

// ---------------- CSR build ----------------
__global__ void csr_count(const int* __restrict__ ei) {
    int i = blockIdx.x * blockDim.x + threadIdx.x;
    if (i >= ET) return;
    int dst = (i < EE) ? ei[EE + i] : i - EE;
    atomicAdd(&g_cnt_i[dst], 1);
}

__global__ void csr_scan() {   // single block, 256 threads, 64 nodes each
    __shared__ int s[256];
    int t = threadIdx.x, base = t * 64;
    int sum = 0;
    for (int i = 0; i < 64; i++) sum += g_cnt_i[base + i];
    s[t] = sum;
    __syncthreads();
    int mysum = sum;
    for (int d = 1; d < 256; d <<= 1) {
        int v = (t >= d) ? s[t - d] : 0;
        __syncthreads();
        s[t] += v;
        __syncthreads();
    }
    int run = s[t] - mysum;     // exclusive prefix
    for (int i = 0; i < 64; i++) {
        int cv = g_cnt_i[base + i];
        g_ptr[base + i] = run;
        g_cnt_i[base + i] = run;  // scatter cursor
        run += cv;
    }
    if (t == 255) g_ptr[NN] = run;
}

__global__ void csr_scatter(const int* __restrict__ ei) {
    int i = blockIdx.x * blockDim.x + threadIdx.x;
    if (i >= ET) return;
    int src, dst;
    if (i < EE) { src = ei[i]; dst = ei[EE + i]; } else { src = i - EE; dst = src; }
    int pos = atomicAdd(&g_cnt_i[dst], 1);
    g_csr_eid[pos] = i;
    g_csr_src[pos] = src;
}

// ---------------- self-loop attr: per-dst mean of incoming real-edge ea -----
__global__ void loop_mean_csr() {
    int n = blockIdx.x, c = threadIdx.x;   // 128 threads
    int s0 = g_ptr[n], s1 = g_ptr[n + 1];
    float acc = 0.0f; int cnt = 0;
    for (int p = s0; p < s1; p++) {
        int e = g_csr_eid[p];
        if (e < EE) { acc += g_ea[(size_t)e * FEE + c]; cnt++; }
    }
    g_ea[(size_t)(EE + n) * FEE + c] = acc / (float)max(cnt, 1);
}

// ---------------- segment softmax over CSR (warp per node) -----------------
__global__ void softmax_csr() {
    int warp = threadIdx.x >> 5, lane = threadIdx.x & 31;
    int n = blockIdx.x * 8 + warp;
    int eo = lane >> 3, h = lane & 7;
    int s0 = g_ptr[n], s1 = g_ptr[n + 1];
    float mx = -3.4e38f;
    for (int p = s0 + eo; p < s1; p += 4)
        mx = fmaxf(mx, g_logit[g_csr_eid[p] * HH + h]);
    mx = fmaxf(mx, __shfl_xor_sync(0xffffffffu, mx, 8));
    mx = fmaxf(mx, __shfl_xor_sync(0xffffffffu, mx, 16));
    float s = 0.0f;
    for (int p = s0 + eo; p < s1; p += 4)
        s += expf(g_logit[g_csr_eid[p] * HH + h] - mx);
    s += __shfl_xor_sync(0xffffffffu, s, 8);
    s += __shfl_xor_sync(0xffffffffu, s, 16);
    float inv = 1.0f / (s + 1e-16f);
    for (int p = s0 + eo; p < s1; p += 4)
        g_alpha[p * HH + h] = expf(g_logit[g_csr_eid[p] * HH + h] - mx) * inv;
}

// ---------------- aggregation + residual + bias + LayerNorm (fused) --------
__global__ void aggregate_ln(const float* __restrict__ gat_bias,
                             const float* __restrict__ gam, const float* __restrict__ beta) {
    int n = blockIdx.x, c = threadIdx.x, h = c >> 5;   // 256 threads
    int s0 = g_ptr[n], s1 = g_ptr[n + 1];
    float acc = 0.0f;
    for (int p = s0; p < s1; p++) {
        float a = g_alpha[p * HH + h];
        int src = g_csr_src[p];
        acc += a * g_xl[(size_t)src * FF + c];
    }
    float v = g_x[(size_t)n * FF + c] + acc + gat_bias[c];
    float s = v, q = v * v;
#pragma unroll
    for (int off = 16; off; off >>= 1) {
        s += __shfl_xor_sync(0xffffffffu, s, off);
        q += __shfl_xor_sync(0xffffffffu, q, off);
    }
    __shared__ float ss[8], sq[8];
    if ((c & 31) == 0) { ss[c >> 5] = s; sq[c >> 5] = q; }
    __syncthreads();
    float S = 0.0f, Q = 0.0f;
#pragma unroll
    for (int i = 0; i < 8; i++) { S += ss[i]; Q += sq[i]; }
    float mu = S * (1.0f / FF);
    float var = Q * (1.0f / FF) - mu * mu;
    g_h[(size_t)n * FF + c] = (v - mu) * rsqrtf(var + 1e-5f) * gam[c] + beta[c];
}

// ---------------- residual + LayerNorm ----------------
__global__ void ln_k(const float* __restrict__ a, const float* __restrict__ b,
                     const float* __restrict__ g, const float* __restrict__ beta,
                     float* __restrict__ o) {
    int n = blockIdx.x, c = threadIdx.x;
    float v = a[(size_t)n * FF + c] + b[(size_t)n * FF + c];
    float s = v, q = v * v;
#pragma unroll
    for (int off = 16; off; off >>= 1) {
        s += __shfl_xor_sync(0xffffffffu, s, off);
        q += __shfl_xor_sync(0xffffffffu, q, off);
    }
    __shared__ float ss[8], sq[8];
    if ((c & 31) == 0) { ss[c >> 5] = s; sq[c >> 5] = q; }
    __syncthreads();
    float S = 0.0f, Q = 0.0f;
#pragma unroll
    for (int i = 0; i < 8; i++) { S += ss[i]; Q += sq[i]; }
    float mu = S * (1.0f / FF);
    float var = Q * (1.0f / FF) - mu * mu;
    o[(size_t)n * FF + c] = (v - mu) * rsqrtf(var + 1e-5f) * g[c] + beta[c];
}

// ---------------- host ----------------
static float* symf(const void* sym) {
    void* p = nullptr;
    cudaGetSymbolAddress(&p, sym);
    return (float*)p;
}

extern "C" void kernel_launch(void* const* d_in, const int* in_sizes, int n_in,
                              void* d_out, int out_size) {
    const float* node_feats  = (const float*)d_in[0];
    const int*   edge_index  = (const int*)d_in[1];
    const float* edge_attr   = (const float*)d_in[2];
    const float* init_node_w = (const float*)d_in[3];
    const float* init_edge_w = (const float*)d_in[4];
    const float* lin_l_w     = (const float*)d_in[5];
    const float* lin_l_b     = (const float*)d_in[6];
    const float* lin_r_w     = (const float*)d_in[7];
    const float* lin_r_b     = (const float*)d_in[8];
    const float* lin_edge_w  = (const float*)d_in[9];
    const float* att         = (const float*)d_in[10];
    const float* gat_bias    = (const float*)d_in[11];
    const float* ln1_g       = (const float*)d_in[12];
    const float* ln1_b       = (const float*)d_in[13];
    const float* mlp_w1      = (const float*)d_in[14];
    const float* mlp_w2      = (const float*)d_in[15];
    const float* ln2_g       = (const float*)d_in[16];
    const float* ln2_b       = (const float*)d_in[17];

    float* px   = symf(g_x);
    float* pxl  = symf(g_xl);
    float* pxr  = symf(g_xr);
    float* ph   = symf(g_h);
    float* py   = symf(g_y);
    float* phid = symf(g_hidden);
    float* pea  = symf(g_ea);
    int*   pcnt = (int*)symf(g_cnt_i);

    // independent up-front work
    gemm_nt<0><<<dim3(FF / 64, NN / 128), 256>>>(node_feats, init_node_w, nullptr, px, NN, FF, FIN_NODE);
    gemm_nt<0><<<dim3(FEE / 64, EE / 128), 256>>>(edge_attr, init_edge_w, nullptr, pea, EE, FEE, FIN_EDGE);

    // CSR build (edges layer-invariant)
    zeroi<<<(NN + 255) / 256, 256>>>(pcnt, NN);
    csr_count<<<(ET + 255) / 256, 256>>>(edge_index);
    csr_scan<<<1, 256>>>();
    csr_scatter<<<(ET + 255) / 256, 256>>>(edge_index);

    // self-loop attrs
    loop_mean_csr<<<NN, FEE>>>();

    for (int l = 0; l < 2; l++) {
        gemm_nt<1><<<dim3(FF / 64, NN / 128), 256>>>(px, lin_l_w + (size_t)l * FF * FF,
                                                     lin_l_b + l * FF, pxl, NN, FF, FF);
        gemm_nt<1><<<dim3(FF / 64, NN / 128), 256>>>(px, lin_r_w + (size_t)l * FF * FF,
                                                     lin_r_b + l * FF, pxr, NN, FF, FF);
        gemm_edge_logit<<<dim3(FF / 64, ET / 128), 256>>>(lin_edge_w + (size_t)l * FF * FEE,
                                                          edge_index, att + l * FF);
        softmax_csr<<<NN / 8, 256>>>();
        aggregate_ln<<<NN, FF>>>(gat_bias + l * FF, ln1_g + l * FF, ln1_b + l * FF);

        gemm_nt<2><<<dim3(512 / 64, NN / 128), 256>>>(ph, mlp_w1 + (size_t)l * 512 * FF,
                                                      nullptr, phid, NN, 512, FF);
        gemm_nt<0><<<dim3(FF / 64, NN / 128), 256>>>(phid, mlp_w2 + (size_t)l * FF * 512,
                                                     nullptr, py, NN, FF, 512);
        float* xo = (l == 1) ? (float*)d_out : px;
        ln_k<<<NN, FF>>>(ph, py, ln2_g + l * FF, ln2_b + l * FF, xo);
    }
}

// round 5
// speedup vs baseline: 2.4890x; 1.2244x over previous
#include <cuda_runtime.h>
#include <cuda_fp16.h>
#include <math.h>

#define NN 16384
#define EE 262144
#define ET (EE + NN)      // 278528
#define FF 256
#define FEE 128
#define HH 8
#define FIN_NODE 768
#define FIN_EDGE 64

// ---------------- scratch (device globals; no allocations) ----------------
__device__ float g_x[NN * FF];
__device__ float g_xl[NN * FF];
__device__ float g_xr[NN * FF];
__device__ float g_h[NN * FF];
__device__ float g_y[NN * FF];
__device__ float g_hidden[NN * 2 * FF];
__device__ float g_ea[ET * FEE];          // projected edge attrs incl. self loops
__device__ float g_logit[ET * HH];
__device__ float g_alpha[ET * HH];
__device__ int   g_cnt_i[NN];
__device__ int   g_ptr[NN + 1];
__device__ int   g_csr_eid[ET];
__device__ int   g_csr_src[ET];

__global__ void zeroi(int* p, int n) {
    int i = blockIdx.x * blockDim.x + threadIdx.x;
    if (i < n) p[i] = 0;
}

// =================== fp16 2-term split tensor-core GEMM ====================
// C[M,Nc] = A[M,K] @ B[Nc,K]^T via mma.sync m16n8k16 f16.
//   A = ah + al (fp16 pair, ~22-bit effective); B = bh (fp16).
//   a*b ≈ ah*bh + al*bh   (fp32 accumulate) -> 2 MMAs per position.
#define SKP 40   // padded smem row (halfs)

__device__ __forceinline__ void mma16816(float c[4], const unsigned a[4], const unsigned b[2]) {
    asm volatile(
        "mma.sync.aligned.m16n8k16.row.col.f32.f16.f16.f32 "
        "{%0,%1,%2,%3},{%4,%5,%6,%7},{%8,%9},{%0,%1,%2,%3};\n"
        : "+f"(c[0]), "+f"(c[1]), "+f"(c[2]), "+f"(c[3])
        : "r"(a[0]), "r"(a[1]), "r"(a[2]), "r"(a[3]), "r"(b[0]), "r"(b[1]));
}

__device__ __forceinline__ void splitA4(float4 v, unsigned& h01, unsigned& h23,
                                        unsigned& l01, unsigned& l23) {
    __half h0 = __float2half_rn(v.x), h1 = __float2half_rn(v.y);
    __half h2 = __float2half_rn(v.z), h3 = __float2half_rn(v.w);
    __half l0 = __float2half_rn(v.x - __half2float(h0));
    __half l1 = __float2half_rn(v.y - __half2float(h1));
    __half l2 = __float2half_rn(v.z - __half2float(h2));
    __half l3 = __float2half_rn(v.w - __half2float(h3));
    h01 = ((unsigned)__half_as_ushort(h1) << 16) | __half_as_ushort(h0);
    h23 = ((unsigned)__half_as_ushort(h3) << 16) | __half_as_ushort(h2);
    l01 = ((unsigned)__half_as_ushort(l1) << 16) | __half_as_ushort(l0);
    l23 = ((unsigned)__half_as_ushort(l3) << 16) | __half_as_ushort(l2);
}
__device__ __forceinline__ void cvtB4(float4 v, unsigned& h01, unsigned& h23) {
    __half h0 = __float2half_rn(v.x), h1 = __float2half_rn(v.y);
    __half h2 = __float2half_rn(v.z), h3 = __float2half_rn(v.w);
    h01 = ((unsigned)__half_as_ushort(h1) << 16) | __half_as_ushort(h0);
    h23 = ((unsigned)__half_as_ushort(h3) << 16) | __half_as_ushort(h2);
}

// Shared mainloop: loads A/B tile, converts, runs 2-term MMA. Accumulates in c.
#define GEMM_MAINLOOP(A, B, K)                                                        \
    for (int k0 = 0; k0 < (K); k0 += 32) {                                            \
        float4 av[4], bv[2];                                                          \
        _Pragma("unroll")                                                             \
        for (int i = 0; i < 4; i++)                                                   \
            av[i] = *(const float4*)&(A)[(size_t)(rowBase + lr + i * 32) * (K) + k0 + lc]; \
        _Pragma("unroll")                                                             \
        for (int i = 0; i < 2; i++)                                                   \
            bv[i] = *(const float4*)&(B)[(size_t)(colBase + lr + i * 32) * (K) + k0 + lc]; \
        __syncthreads();                                                              \
        _Pragma("unroll")                                                             \
        for (int i = 0; i < 4; i++) {                                                 \
            unsigned h01, h23, l01, l23;                                              \
            splitA4(av[i], h01, h23, l01, l23);                                       \
            *(uint2*)&Ah[lr + i * 32][lc] = make_uint2(h01, h23);                     \
            *(uint2*)&Al[lr + i * 32][lc] = make_uint2(l01, l23);                     \
        }                                                                             \
        _Pragma("unroll")                                                             \
        for (int i = 0; i < 2; i++) {                                                 \
            unsigned h01, h23;                                                        \
            cvtB4(bv[i], h01, h23);                                                   \
            *(uint2*)&Bh[lr + i * 32][lc] = make_uint2(h01, h23);                     \
        }                                                                             \
        __syncthreads();                                                              \
        _Pragma("unroll")                                                             \
        for (int kk = 0; kk < 2; kk++) {                                              \
            unsigned ah[2][4], al[2][4], bh[4][2];                                    \
            const int kf = kk * 16 + tg * 2;                                          \
            _Pragma("unroll")                                                         \
            for (int mi = 0; mi < 2; mi++) {                                          \
                int m = wm * 32 + mi * 16 + g;                                        \
                ah[mi][0] = *(const unsigned*)&Ah[m][kf];                             \
                ah[mi][1] = *(const unsigned*)&Ah[m + 8][kf];                         \
                ah[mi][2] = *(const unsigned*)&Ah[m][kf + 8];                         \
                ah[mi][3] = *(const unsigned*)&Ah[m + 8][kf + 8];                     \
                al[mi][0] = *(const unsigned*)&Al[m][kf];                             \
                al[mi][1] = *(const unsigned*)&Al[m + 8][kf];                         \
                al[mi][2] = *(const unsigned*)&Al[m][kf + 8];                         \
                al[mi][3] = *(const unsigned*)&Al[m + 8][kf + 8];                     \
            }                                                                         \
            _Pragma("unroll")                                                         \
            for (int ni = 0; ni < 4; ni++) {                                          \
                int n = wn * 32 + ni * 8 + g;                                         \
                bh[ni][0] = *(const unsigned*)&Bh[n][kf];                             \
                bh[ni][1] = *(const unsigned*)&Bh[n][kf + 8];                         \
            }                                                                         \
            _Pragma("unroll")                                                         \
            for (int mi = 0; mi < 2; mi++)                                            \
                _Pragma("unroll")                                                     \
                for (int ni = 0; ni < 4; ni++) {                                      \
                    mma16816(c[mi][ni], ah[mi], bh[ni]);                              \
                    mma16816(c[mi][ni], al[mi], bh[ni]);                              \
                }                                                                     \
        }                                                                             \
    }

// C = A @ B^T (+epi).  EPI: 0 none, 1 +bias, 2 gelu
template <int EPI>
__global__ __launch_bounds__(256)
void gemm_nt(const float* __restrict__ A, const float* __restrict__ B,
             const float* __restrict__ bias, float* __restrict__ C,
             int M, int Nc, int K) {
    __shared__ __half Ah[128][SKP], Al[128][SKP];
    __shared__ __half Bh[64][SKP];
    const int tid = threadIdx.x, lane = tid & 31, w = tid >> 5;
    const int wm = w >> 1, wn = w & 1;
    const int rowBase = blockIdx.y * 128, colBase = blockIdx.x * 64;
    const int g = lane >> 2, tg = lane & 3;
    const int lr = tid >> 3, lc = (tid & 7) * 4;
    float c[2][4][4] = {};
    GEMM_MAINLOOP(A, B, K)
#pragma unroll
    for (int mi = 0; mi < 2; mi++)
#pragma unroll
        for (int ni = 0; ni < 4; ni++) {
            int col = colBase + wn * 32 + ni * 8 + tg * 2;
            float b0 = 0.f, b1 = 0.f;
            if (EPI == 1) { b0 = bias[col]; b1 = bias[col + 1]; }
#pragma unroll
            for (int half = 0; half < 2; half++) {
                int row = rowBase + wm * 32 + mi * 16 + g + half * 8;
                float v0 = c[mi][ni][half * 2] + b0;
                float v1 = c[mi][ni][half * 2 + 1] + b1;
                if (EPI == 2) {
                    v0 = 0.5f * v0 * (1.0f + erff(v0 * 0.70710678118654752f));
                    v1 = 0.5f * v1 * (1.0f + erff(v1 * 0.70710678118654752f));
                }
                *(float2*)&C[(size_t)row * Nc + col] = make_float2(v0, v1);
            }
        }
}

// Fused: eemb = g_ea @ W_edge^T, then logits = sum_c leakyrelu(xl[src]+xr[dst]+eemb)*att
// Writes g_logit[e, h] directly; each warp owns one head -> no atomics, no eemb buffer.
__global__ __launch_bounds__(256)
void gemm_edge_logit(const float* __restrict__ B, const int* __restrict__ ei,
                     const float* __restrict__ att) {
    __shared__ __half Ah[128][SKP], Al[128][SKP];
    __shared__ __half Bh[64][SKP];
    const int tid = threadIdx.x, lane = tid & 31, w = tid >> 5;
    const int wm = w >> 1, wn = w & 1;
    const int rowBase = blockIdx.y * 128, colBase = blockIdx.x * 64;
    const int g = lane >> 2, tg = lane & 3;
    const int lr = tid >> 3, lc = (tid & 7) * 4;
    const float* A = g_ea;
    float c[2][4][4] = {};
    GEMM_MAINLOOP(A, B, FEE)

    // epilogue: fused logit
    const int head = (colBase >> 5) + wn;
    float attv[4][2];
#pragma unroll
    for (int ni = 0; ni < 4; ni++) {
        int col = colBase + wn * 32 + ni * 8 + tg * 2;
        attv[ni][0] = att[col]; attv[ni][1] = att[col + 1];
    }
#pragma unroll
    for (int mi = 0; mi < 2; mi++)
#pragma unroll
        for (int half = 0; half < 2; half++) {
            int r = rowBase + wm * 32 + mi * 16 + g + half * 8;
            int src, dst;
            if (r < EE) { src = __ldg(&ei[r]); dst = __ldg(&ei[EE + r]); }
            else { src = r - EE; dst = src; }
            const float* xl = &g_xl[(size_t)src * FF];
            const float* xr = &g_xr[(size_t)dst * FF];
            float part = 0.0f;
#pragma unroll
            for (int ni = 0; ni < 4; ni++) {
                int col = colBase + wn * 32 + ni * 8 + tg * 2;
                float2 xlv = *(const float2*)&xl[col];
                float2 xrv = *(const float2*)&xr[col];
                float m0 = c[mi][ni][half * 2]     + xlv.x + xrv.x;
                float m1 = c[mi][ni][half * 2 + 1] + xlv.y + xrv.y;
                m0 = m0 >= 0.0f ? m0 : 0.2f * m0;
                m1 = m1 >= 0.0f ? m1 : 0.2f * m1;
                part += m0 * attv[ni][0] + m1 * attv[ni][1];
            }
            part += __shfl_xor_sync(0xffffffffu, part, 1);
            part += __shfl_xor_sync(0xffffffffu, part, 2);
            if (tg == 0) g_logit[r * HH + head] = part;
        }
}

// ---------------- CSR build ----------------
__global__ void csr_count(const int* __restrict__ ei) {
    int i = blockIdx.x * blockDim.x + threadIdx.x;
    if (i >= ET) return;
    int dst = (i < EE) ? ei[EE + i] : i - EE;
    atomicAdd(&g_cnt_i[dst], 1);
}

__global__ void csr_scan() {   // single block, 256 threads, 64 nodes each
    __shared__ int s[256];
    int t = threadIdx.x, base = t * 64;
    int sum = 0;
    for (int i = 0; i < 64; i++) sum += g_cnt_i[base + i];
    s[t] = sum;
    __syncthreads();
    int mysum = sum;
    for (int d = 1; d < 256; d <<= 1) {
        int v = (t >= d) ? s[t - d] : 0;
        __syncthreads();
        s[t] += v;
        __syncthreads();
    }
    int run = s[t] - mysum;
    for (int i = 0; i < 64; i++) {
        int cv = g_cnt_i[base + i];
        g_ptr[base + i] = run;
        g_cnt_i[base + i] = run;
        run += cv;
    }
    if (t == 255) g_ptr[NN] = run;
}

__global__ void csr_scatter(const int* __restrict__ ei) {
    int i = blockIdx.x * blockDim.x + threadIdx.x;
    if (i >= ET) return;
    int src, dst;
    if (i < EE) { src = ei[i]; dst = ei[EE + i]; } else { src = i - EE; dst = src; }
    int pos = atomicAdd(&g_cnt_i[dst], 1);
    g_csr_eid[pos] = i;
    g_csr_src[pos] = src;
}

// ---------------- self-loop attr: per-dst mean of incoming real-edge ea -----
__global__ void loop_mean_csr() {
    int n = blockIdx.x, c = threadIdx.x;   // 128 threads
    int s0 = g_ptr[n], s1 = g_ptr[n + 1];
    float acc = 0.0f; int cnt = 0;
    for (int p = s0; p < s1; p++) {
        int e = g_csr_eid[p];
        if (e < EE) { acc += g_ea[(size_t)e * FEE + c]; cnt++; }
    }
    g_ea[(size_t)(EE + n) * FEE + c] = acc / (float)max(cnt, 1);
}

// ---------------- segment softmax over CSR (warp per node) -----------------
__global__ void softmax_csr() {
    int warp = threadIdx.x >> 5, lane = threadIdx.x & 31;
    int n = blockIdx.x * 8 + warp;
    int eo = lane >> 3, h = lane & 7;
    int s0 = g_ptr[n], s1 = g_ptr[n + 1];
    float mx = -3.4e38f;
    for (int p = s0 + eo; p < s1; p += 4)
        mx = fmaxf(mx, g_logit[g_csr_eid[p] * HH + h]);
    mx = fmaxf(mx, __shfl_xor_sync(0xffffffffu, mx, 8));
    mx = fmaxf(mx, __shfl_xor_sync(0xffffffffu, mx, 16));
    float s = 0.0f;
    for (int p = s0 + eo; p < s1; p += 4)
        s += expf(g_logit[g_csr_eid[p] * HH + h] - mx);
    s += __shfl_xor_sync(0xffffffffu, s, 8);
    s += __shfl_xor_sync(0xffffffffu, s, 16);
    float inv = 1.0f / (s + 1e-16f);
    for (int p = s0 + eo; p < s1; p += 4)
        g_alpha[p * HH + h] = expf(g_logit[g_csr_eid[p] * HH + h] - mx) * inv;
}

// ---------------- aggregation + residual + bias + LayerNorm (fused) --------
__global__ void aggregate_ln(const float* __restrict__ gat_bias,
                             const float* __restrict__ gam, const float* __restrict__ beta) {
    int n = blockIdx.x, c = threadIdx.x, h = c >> 5;   // 256 threads
    int s0 = g_ptr[n], s1 = g_ptr[n + 1];
    float acc = 0.0f;
    for (int p = s0; p < s1; p++) {
        float a = g_alpha[p * HH + h];
        int src = g_csr_src[p];
        acc += a * g_xl[(size_t)src * FF + c];
    }
    float v = g_x[(size_t)n * FF + c] + acc + gat_bias[c];
    float s = v, q = v * v;
#pragma unroll
    for (int off = 16; off; off >>= 1) {
        s += __shfl_xor_sync(0xffffffffu, s, off);
        q += __shfl_xor_sync(0xffffffffu, q, off);
    }
    __shared__ float ss[8], sq[8];
    if ((c & 31) == 0) { ss[c >> 5] = s; sq[c >> 5] = q; }
    __syncthreads();
    float S = 0.0f, Q = 0.0f;
#pragma unroll
    for (int i = 0; i < 8; i++) { S += ss[i]; Q += sq[i]; }
    float mu = S * (1.0f / FF);
    float var = Q * (1.0f / FF) - mu * mu;
    g_h[(size_t)n * FF + c] = (v - mu) * rsqrtf(var + 1e-5f) * gam[c] + beta[c];
}

// ---------------- residual + LayerNorm ----------------
__global__ void ln_k(const float* __restrict__ a, const float* __restrict__ b,
                     const float* __restrict__ g, const float* __restrict__ beta,
                     float* __restrict__ o) {
    int n = blockIdx.x, c = threadIdx.x;
    float v = a[(size_t)n * FF + c] + b[(size_t)n * FF + c];
    float s = v, q = v * v;
#pragma unroll
    for (int off = 16; off; off >>= 1) {
        s += __shfl_xor_sync(0xffffffffu, s, off);
        q += __shfl_xor_sync(0xffffffffu, q, off);
    }
    __shared__ float ss[8], sq[8];
    if ((c & 31) == 0) { ss[c >> 5] = s; sq[c >> 5] = q; }
    __syncthreads();
    float S = 0.0f, Q = 0.0f;
#pragma unroll
    for (int i = 0; i < 8; i++) { S += ss[i]; Q += sq[i]; }
    float mu = S * (1.0f / FF);
    float var = Q * (1.0f / FF) - mu * mu;
    o[(size_t)n * FF + c] = (v - mu) * rsqrtf(var + 1e-5f) * g[c] + beta[c];
}

// ---------------- host ----------------
static float* symf(const void* sym) {
    void* p = nullptr;
    cudaGetSymbolAddress(&p, sym);
    return (float*)p;
}

extern "C" void kernel_launch(void* const* d_in, const int* in_sizes, int n_in,
                              void* d_out, int out_size) {
    const float* node_feats  = (const float*)d_in[0];
    const int*   edge_index  = (const int*)d_in[1];
    const float* edge_attr   = (const float*)d_in[2];
    const float* init_node_w = (const float*)d_in[3];
    const float* init_edge_w = (const float*)d_in[4];
    const float* lin_l_w     = (const float*)d_in[5];
    const float* lin_l_b     = (const float*)d_in[6];
    const float* lin_r_w     = (const float*)d_in[7];
    const float* lin_r_b     = (const float*)d_in[8];
    const float* lin_edge_w  = (const float*)d_in[9];
    const float* att         = (const float*)d_in[10];
    const float* gat_bias    = (const float*)d_in[11];
    const float* ln1_g       = (const float*)d_in[12];
    const float* ln1_b       = (const float*)d_in[13];
    const float* mlp_w1      = (const float*)d_in[14];
    const float* mlp_w2      = (const float*)d_in[15];
    const float* ln2_g       = (const float*)d_in[16];
    const float* ln2_b       = (const float*)d_in[17];

    float* px   = symf(g_x);
    float* pxl  = symf(g_xl);
    float* pxr  = symf(g_xr);
    float* ph   = symf(g_h);
    float* py   = symf(g_y);
    float* phid = symf(g_hidden);
    float* pea  = symf(g_ea);
    int*   pcnt = (int*)symf(g_cnt_i);

    // independent up-front work
    gemm_nt<0><<<dim3(FF / 64, NN / 128), 256>>>(node_feats, init_node_w, nullptr, px, NN, FF, FIN_NODE);
    gemm_nt<0><<<dim3(FEE / 64, EE / 128), 256>>>(edge_attr, init_edge_w, nullptr, pea, EE, FEE, FIN_EDGE);

    // CSR build (edges layer-invariant)
    zeroi<<<(NN + 255) / 256, 256>>>(pcnt, NN);
    csr_count<<<(ET + 255) / 256, 256>>>(edge_index);
    csr_scan<<<1, 256>>>();
    csr_scatter<<<(ET + 255) / 256, 256>>>(edge_index);

    // self-loop attrs
    loop_mean_csr<<<NN, FEE>>>();

    for (int l = 0; l < 2; l++) {
        gemm_nt<1><<<dim3(FF / 64, NN / 128), 256>>>(px, lin_l_w + (size_t)l * FF * FF,
                                                     lin_l_b + l * FF, pxl, NN, FF, FF);
        gemm_nt<1><<<dim3(FF / 64, NN / 128), 256>>>(px, lin_r_w + (size_t)l * FF * FF,
                                                     lin_r_b + l * FF, pxr, NN, FF, FF);
        gemm_edge_logit<<<dim3(FF / 64, ET / 128), 256>>>(lin_edge_w + (size_t)l * FF * FEE,
                                                          edge_index, att + l * FF);
        softmax_csr<<<NN / 8, 256>>>();
        aggregate_ln<<<NN, FF>>>(gat_bias + l * FF, ln1_g + l * FF, ln1_b + l * FF);

        gemm_nt<2><<<dim3(512 / 64, NN / 128), 256>>>(ph, mlp_w1 + (size_t)l * 512 * FF,
                                                      nullptr, phid, NN, 512, FF);
        gemm_nt<0><<<dim3(FF / 64, NN / 128), 256>>>(phid, mlp_w2 + (size_t)l * FF * 512,
                                                     nullptr, py, NN, FF, 512);
        float* xo = (l == 1) ? (float*)d_out : px;
        ln_k<<<NN, FF>>>(ph, py, ln2_g + l * FF, ln2_b + l * FF, xo);
    }
}

// round 7
// speedup vs baseline: 2.5870x; 1.0394x over previous
#include <cuda_runtime.h>
#include <cuda_fp16.h>
#include <math.h>

#define NN 16384
#define EE 262144
#define ET (EE + NN)      // 278528
#define FF 256
#define FEE 128
#define HH 8
#define FIN_NODE 768
#define FIN_EDGE 64

// ---------------- scratch (device globals; no allocations) ----------------
__device__ float g_x[NN * FF];
__device__ float g_xl[NN * FF];
__device__ float g_xr[NN * FF];
__device__ float g_h[NN * FF];
__device__ float g_y[NN * FF];
__device__ float g_hidden[NN * 2 * FF];
__device__ __half g_eah[(size_t)ET * FEE];  // projected edge attrs, fp16 hi
__device__ __half g_eal[(size_t)ET * FEE];  // fp16 lo residual
__device__ float g_logit[ET * HH];
__device__ float g_alpha[ET * HH];
__device__ int   g_cnt_i[NN];
__device__ int   g_ptr[NN + 1];
__device__ int   g_csr_eid[ET];
__device__ int   g_csr_src[ET];

__global__ void zeroi(int* p, int n) {
    int i = blockIdx.x * blockDim.x + threadIdx.x;
    if (i < n) p[i] = 0;
}

// =================== fp16 2-term split tensor-core GEMM ====================
#define SKP 40   // padded smem row (halfs)

__device__ __forceinline__ void mma16816(float c[4], const unsigned a[4], const unsigned b[2]) {
    asm volatile(
        "mma.sync.aligned.m16n8k16.row.col.f32.f16.f16.f32 "
        "{%0,%1,%2,%3},{%4,%5,%6,%7},{%8,%9},{%0,%1,%2,%3};\n"
        : "+f"(c[0]), "+f"(c[1]), "+f"(c[2]), "+f"(c[3])
        : "r"(a[0]), "r"(a[1]), "r"(a[2]), "r"(a[3]), "r"(b[0]), "r"(b[1]));
}

__device__ __forceinline__ void splitA4(float4 v, unsigned& h01, unsigned& h23,
                                        unsigned& l01, unsigned& l23) {
    __half h0 = __float2half_rn(v.x), h1 = __float2half_rn(v.y);
    __half h2 = __float2half_rn(v.z), h3 = __float2half_rn(v.w);
    __half l0 = __float2half_rn(v.x - __half2float(h0));
    __half l1 = __float2half_rn(v.y - __half2float(h1));
    __half l2 = __float2half_rn(v.z - __half2float(h2));
    __half l3 = __float2half_rn(v.w - __half2float(h3));
    h01 = ((unsigned)__half_as_ushort(h1) << 16) | __half_as_ushort(h0);
    h23 = ((unsigned)__half_as_ushort(h3) << 16) | __half_as_ushort(h2);
    l01 = ((unsigned)__half_as_ushort(l1) << 16) | __half_as_ushort(l0);
    l23 = ((unsigned)__half_as_ushort(l3) << 16) | __half_as_ushort(l2);
}
__device__ __forceinline__ void cvtB4(float4 v, unsigned& h01, unsigned& h23) {
    __half h0 = __float2half_rn(v.x), h1 = __float2half_rn(v.y);
    __half h2 = __float2half_rn(v.z), h3 = __float2half_rn(v.w);
    h01 = ((unsigned)__half_as_ushort(h1) << 16) | __half_as_ushort(h0);
    h23 = ((unsigned)__half_as_ushort(h3) << 16) | __half_as_ushort(h2);
}

// Mainloop over fp32 A (split in-loop) and fp32 B. Tile 128x64.
#define GEMM_MAINLOOP(A, B, K)                                                        \
    for (int k0 = 0; k0 < (K); k0 += 32) {                                            \
        float4 av[4], bv[2];                                                          \
        _Pragma("unroll")                                                             \
        for (int i = 0; i < 4; i++)                                                   \
            av[i] = *(const float4*)&(A)[(size_t)(rowBase + lr + i * 32) * (K) + k0 + lc]; \
        _Pragma("unroll")                                                             \
        for (int i = 0; i < 2; i++)                                                   \
            bv[i] = *(const float4*)&(B)[(size_t)(colBase + lr + i * 32) * (K) + k0 + lc]; \
        __syncthreads();                                                              \
        _Pragma("unroll")                                                             \
        for (int i = 0; i < 4; i++) {                                                 \
            unsigned h01, h23, l01, l23;                                              \
            splitA4(av[i], h01, h23, l01, l23);                                       \
            *(uint2*)&Ah[lr + i * 32][lc] = make_uint2(h01, h23);                     \
            *(uint2*)&Al[lr + i * 32][lc] = make_uint2(l01, l23);                     \
        }                                                                             \
        _Pragma("unroll")                                                             \
        for (int i = 0; i < 2; i++) {                                                 \
            unsigned h01, h23;                                                        \
            cvtB4(bv[i], h01, h23);                                                   \
            *(uint2*)&Bh[lr + i * 32][lc] = make_uint2(h01, h23);                     \
        }                                                                             \
        __syncthreads();                                                              \
        _Pragma("unroll")                                                             \
        for (int kk = 0; kk < 2; kk++) {                                              \
            unsigned ah[2][4], al[2][4], bh[4][2];                                    \
            const int kf = kk * 16 + tg * 2;                                          \
            _Pragma("unroll")                                                         \
            for (int mi = 0; mi < 2; mi++) {                                          \
                int m = wm * 32 + mi * 16 + g;                                        \
                ah[mi][0] = *(const unsigned*)&Ah[m][kf];                             \
                ah[mi][1] = *(const unsigned*)&Ah[m + 8][kf];                         \
                ah[mi][2] = *(const unsigned*)&Ah[m][kf + 8];                         \
                ah[mi][3] = *(const unsigned*)&Ah[m + 8][kf + 8];                     \
                al[mi][0] = *(const unsigned*)&Al[m][kf];                             \
                al[mi][1] = *(const unsigned*)&Al[m + 8][kf];                         \
                al[mi][2] = *(const unsigned*)&Al[m][kf + 8];                         \
                al[mi][3] = *(const unsigned*)&Al[m + 8][kf + 8];                     \
            }                                                                         \
            _Pragma("unroll")                                                         \
            for (int ni = 0; ni < 4; ni++) {                                          \
                int n = wn * 32 + ni * 8 + g;                                         \
                bh[ni][0] = *(const unsigned*)&Bh[n][kf];                             \
                bh[ni][1] = *(const unsigned*)&Bh[n][kf + 8];                         \
            }                                                                         \
            _Pragma("unroll")                                                         \
            for (int mi = 0; mi < 2; mi++)                                            \
                _Pragma("unroll")                                                     \
                for (int ni = 0; ni < 4; ni++) {                                      \
                    mma16816(c[mi][ni], ah[mi], bh[ni]);                              \
                    mma16816(c[mi][ni], al[mi], bh[ni]);                              \
                }                                                                     \
        }                                                                             \
    }

// C = A @ B^T (+epi).  EPI: 0 none, 1 +bias, 2 gelu, 3 split-half out to g_eah/g_eal
template <int EPI>
__global__ __launch_bounds__(256)
void gemm_nt(const float* __restrict__ A, const float* __restrict__ B,
             const float* __restrict__ bias, float* __restrict__ C,
             int M, int Nc, int K) {
    __shared__ __half Ah[128][SKP], Al[128][SKP];
    __shared__ __half Bh[64][SKP];
    const int tid = threadIdx.x, lane = tid & 31, w = tid >> 5;
    const int wm = w >> 1, wn = w & 1;
    const int rowBase = blockIdx.y * 128, colBase = blockIdx.x * 64;
    const int g = lane >> 2, tg = lane & 3;
    const int lr = tid >> 3, lc = (tid & 7) * 4;
    float c[2][4][4] = {};
    GEMM_MAINLOOP(A, B, K)
#pragma unroll
    for (int mi = 0; mi < 2; mi++)
#pragma unroll
        for (int ni = 0; ni < 4; ni++) {
            int col = colBase + wn * 32 + ni * 8 + tg * 2;
            float b0 = 0.f, b1 = 0.f;
            if (EPI == 1) { b0 = bias[col]; b1 = bias[col + 1]; }
#pragma unroll
            for (int half = 0; half < 2; half++) {
                int row = rowBase + wm * 32 + mi * 16 + g + half * 8;
                float v0 = c[mi][ni][half * 2] + b0;
                float v1 = c[mi][ni][half * 2 + 1] + b1;
                if (EPI == 2) {
                    v0 = 0.5f * v0 * (1.0f + erff(v0 * 0.70710678118654752f));
                    v1 = 0.5f * v1 * (1.0f + erff(v1 * 0.70710678118654752f));
                }
                if (EPI == 3) {
                    __half h0 = __float2half_rn(v0), h1 = __float2half_rn(v1);
                    __half e0 = __float2half_rn(v0 - __half2float(h0));
                    __half e1 = __float2half_rn(v1 - __half2float(h1));
                    *(__half2*)&g_eah[(size_t)row * FEE + col] = __halves2half2(h0, h1);
                    *(__half2*)&g_eal[(size_t)row * FEE + col] = __halves2half2(e0, e1);
                } else {
                    *(float2*)&C[(size_t)row * Nc + col] = make_float2(v0, v1);
                }
            }
        }
}

// Dual-output node projection: xl = x@Wl^T+bl, xr = x@Wr^T+br in one launch.
__global__ __launch_bounds__(256)
void gemm_dual(const float* __restrict__ A,
               const float* __restrict__ B1, const float* __restrict__ b1, float* __restrict__ C1,
               const float* __restrict__ B2, const float* __restrict__ b2, float* __restrict__ C2) {
    __shared__ __half Ah[128][SKP], Al[128][SKP];
    __shared__ __half Bh[64][SKP];
    const int tid = threadIdx.x, lane = tid & 31, w = tid >> 5;
    const int wm = w >> 1, wn = w & 1;
    const int rowBase = blockIdx.y * 128;
    const bool second = blockIdx.x >= 4;
    const int colBase = (blockIdx.x & 3) * 64;
    const float* B = second ? B2 : B1;
    const float* bias = second ? b2 : b1;
    float* C = second ? C2 : C1;
    const int g = lane >> 2, tg = lane & 3;
    const int lr = tid >> 3, lc = (tid & 7) * 4;
    float c[2][4][4] = {};
    GEMM_MAINLOOP(A, B, FF)
#pragma unroll
    for (int mi = 0; mi < 2; mi++)
#pragma unroll
        for (int ni = 0; ni < 4; ni++) {
            int col = colBase + wn * 32 + ni * 8 + tg * 2;
            float b0 = bias[col], b1v = bias[col + 1];
#pragma unroll
            for (int half = 0; half < 2; half++) {
                int row = rowBase + wm * 32 + mi * 16 + g + half * 8;
                *(float2*)&C[(size_t)row * FF + col] =
                    make_float2(c[mi][ni][half * 2] + b0, c[mi][ni][half * 2 + 1] + b1v);
            }
        }
}

// Fused edge GEMM + GATv2 logits. A pre-split (g_eah/g_eal), tile 128x128.
__global__ __launch_bounds__(256)
void gemm_edge_logit(const float* __restrict__ B, const int* __restrict__ ei,
                     const float* __restrict__ att) {
    __shared__ __half Ah[128][SKP], Al[128][SKP];
    __shared__ __half Bh[128][SKP];
    const int tid = threadIdx.x, lane = tid & 31, w = tid >> 5;
    const int wm = w >> 1, wn = w & 1;              // wm 0..3 (32 rows), wn 0..1 (64 cols)
    const int rowBase = blockIdx.y * 128, colBase = blockIdx.x * 128;
    const int g = lane >> 2, tg = lane & 3;
    float c[2][8][4] = {};

    const int lr8 = tid >> 3, lc8 = (tid & 7) * 4;  // 32 rows x 8 4-half cols per pass

    for (int k0 = 0; k0 < FEE; k0 += 32) {
        __syncthreads();
#pragma unroll
        for (int i = 0; i < 4; i++) {               // cover all 128 rows
            int r = lr8 + i * 32;
            *(uint2*)&Ah[r][lc8] = *(const uint2*)&g_eah[(size_t)(rowBase + r) * FEE + k0 + lc8];
            *(uint2*)&Al[r][lc8] = *(const uint2*)&g_eal[(size_t)(rowBase + r) * FEE + k0 + lc8];
            float4 bv = *(const float4*)&B[(size_t)(colBase + r) * FEE + k0 + lc8];
            unsigned h01, h23;
            cvtB4(bv, h01, h23);
            *(uint2*)&Bh[r][lc8] = make_uint2(h01, h23);
        }
        __syncthreads();
#pragma unroll
        for (int kk = 0; kk < 2; kk++) {
            unsigned ah[2][4], al[2][4], bh[8][2];
            const int kf = kk * 16 + tg * 2;
#pragma unroll
            for (int mi = 0; mi < 2; mi++) {
                int m = wm * 32 + mi * 16 + g;
                ah[mi][0] = *(const unsigned*)&Ah[m][kf];
                ah[mi][1] = *(const unsigned*)&Ah[m + 8][kf];
                ah[mi][2] = *(const unsigned*)&Ah[m][kf + 8];
                ah[mi][3] = *(const unsigned*)&Ah[m + 8][kf + 8];
                al[mi][0] = *(const unsigned*)&Al[m][kf];
                al[mi][1] = *(const unsigned*)&Al[m + 8][kf];
                al[mi][2] = *(const unsigned*)&Al[m][kf + 8];
                al[mi][3] = *(const unsigned*)&Al[m + 8][kf + 8];
            }
#pragma unroll
            for (int ni = 0; ni < 8; ni++) {
                int n = wn * 64 + ni * 8 + g;
                bh[ni][0] = *(const unsigned*)&Bh[n][kf];
                bh[ni][1] = *(const unsigned*)&Bh[n][kf + 8];
            }
#pragma unroll
            for (int mi = 0; mi < 2; mi++)
#pragma unroll
                for (int ni = 0; ni < 8; ni++) {
                    mma16816(c[mi][ni], ah[mi], bh[ni]);
                    mma16816(c[mi][ni], al[mi], bh[ni]);
                }
        }
    }

    // epilogue: two heads per warp (cols wn*64 .. +63)
    const int headBase = (colBase >> 5) + wn * 2;
    float attv[8][2];
#pragma unroll
    for (int ni = 0; ni < 8; ni++) {
        int col = colBase + wn * 64 + ni * 8 + tg * 2;
        attv[ni][0] = att[col]; attv[ni][1] = att[col + 1];
    }
#pragma unroll
    for (int mi = 0; mi < 2; mi++)
#pragma unroll
        for (int half = 0; half < 2; half++) {
            int r = rowBase + wm * 32 + mi * 16 + g + half * 8;
            int src, dst;
            if (r < EE) { src = __ldg(&ei[r]); dst = __ldg(&ei[EE + r]); }
            else { src = r - EE; dst = src; }
            const float* xl = &g_xl[(size_t)src * FF];
            const float* xr = &g_xr[(size_t)dst * FF];
            float p0 = 0.0f, p1 = 0.0f;
#pragma unroll
            for (int ni = 0; ni < 8; ni++) {
                int col = colBase + wn * 64 + ni * 8 + tg * 2;
                float2 xlv = *(const float2*)&xl[col];
                float2 xrv = *(const float2*)&xr[col];
                float m0 = c[mi][ni][half * 2]     + xlv.x + xrv.x;
                float m1 = c[mi][ni][half * 2 + 1] + xlv.y + xrv.y;
                m0 = m0 >= 0.0f ? m0 : 0.2f * m0;
                m1 = m1 >= 0.0f ? m1 : 0.2f * m1;
                float t = m0 * attv[ni][0] + m1 * attv[ni][1];
                if (ni < 4) p0 += t; else p1 += t;
            }
            p0 += __shfl_xor_sync(0xffffffffu, p0, 1);
            p0 += __shfl_xor_sync(0xffffffffu, p0, 2);
            p1 += __shfl_xor_sync(0xffffffffu, p1, 1);
            p1 += __shfl_xor_sync(0xffffffffu, p1, 2);
            if (tg == 0) {
                g_logit[r * HH + headBase]     = p0;
                g_logit[r * HH + headBase + 1] = p1;
            }
        }
}

// ---------------- CSR build ----------------
__global__ void csr_count(const int* __restrict__ ei) {
    int i = blockIdx.x * blockDim.x + threadIdx.x;
    if (i >= ET) return;
    int dst = (i < EE) ? ei[EE + i] : i - EE;
    atomicAdd(&g_cnt_i[dst], 1);
}

__global__ void csr_scan() {
    __shared__ int s[256];
    int t = threadIdx.x, base = t * 64;
    int sum = 0;
    for (int i = 0; i < 64; i++) sum += g_cnt_i[base + i];
    s[t] = sum;
    __syncthreads();
    int mysum = sum;
    for (int d = 1; d < 256; d <<= 1) {
        int v = (t >= d) ? s[t - d] : 0;
        __syncthreads();
        s[t] += v;
        __syncthreads();
    }
    int run = s[t] - mysum;
    for (int i = 0; i < 64; i++) {
        int cv = g_cnt_i[base + i];
        g_ptr[base + i] = run;
        g_cnt_i[base + i] = run;
        run += cv;
    }
    if (t == 255) g_ptr[NN] = run;
}

__global__ void csr_scatter(const int* __restrict__ ei) {
    int i = blockIdx.x * blockDim.x + threadIdx.x;
    if (i >= ET) return;
    int src, dst;
    if (i < EE) { src = ei[i]; dst = ei[EE + i]; } else { src = i - EE; dst = src; }
    int pos = atomicAdd(&g_cnt_i[dst], 1);
    g_csr_eid[pos] = i;
    g_csr_src[pos] = src;
}

// ---------------- self-loop attr: per-dst mean of incoming real-edge ea -----
__global__ void loop_mean_csr() {
    int n = blockIdx.x, c = threadIdx.x;   // 128 threads
    int s0 = g_ptr[n], s1 = g_ptr[n + 1];
    float acc = 0.0f; int cnt = 0;
    for (int p = s0; p < s1; p++) {
        int e = g_csr_eid[p];
        if (e < EE) {
            acc += __half2float(g_eah[(size_t)e * FEE + c]) +
                   __half2float(g_eal[(size_t)e * FEE + c]);
            cnt++;
        }
    }
    float v = acc / (float)max(cnt, 1);
    __half h = __float2half_rn(v);
    g_eah[(size_t)(EE + n) * FEE + c] = h;
    g_eal[(size_t)(EE + n) * FEE + c] = __float2half_rn(v - __half2float(h));
}

// ---------------- segment softmax over CSR (warp per node) -----------------
__global__ void softmax_csr() {
    int warp = threadIdx.x >> 5, lane = threadIdx.x & 31;
    int n = blockIdx.x * 8 + warp;
    int eo = lane >> 3, h = lane & 7;
    int s0 = g_ptr[n], s1 = g_ptr[n + 1];
    float mx = -3.4e38f;
    for (int p = s0 + eo; p < s1; p += 4)
        mx = fmaxf(mx, g_logit[g_csr_eid[p] * HH + h]);
    mx = fmaxf(mx, __shfl_xor_sync(0xffffffffu, mx, 8));
    mx = fmaxf(mx, __shfl_xor_sync(0xffffffffu, mx, 16));
    float s = 0.0f;
    for (int p = s0 + eo; p < s1; p += 4)
        s += expf(g_logit[g_csr_eid[p] * HH + h] - mx);
    s += __shfl_xor_sync(0xffffffffu, s, 8);
    s += __shfl_xor_sync(0xffffffffu, s, 16);
    float inv = 1.0f / (s + 1e-16f);
    for (int p = s0 + eo; p < s1; p += 4)
        g_alpha[p * HH + h] = expf(g_logit[g_csr_eid[p] * HH + h] - mx) * inv;
}

// ---------------- aggregation + residual + bias + LayerNorm (fused) --------
__global__ void aggregate_ln(const float* __restrict__ gat_bias,
                             const float* __restrict__ gam, const float* __restrict__ beta) {
    int n = blockIdx.x, c = threadIdx.x, h = c >> 5;
    int s0 = g_ptr[n], s1 = g_ptr[n + 1];
    float acc = 0.0f;
    for (int p = s0; p < s1; p++) {
        float a = g_alpha[p * HH + h];
        int src = g_csr_src[p];
        acc += a * g_xl[(size_t)src * FF + c];
    }
    float v = g_x[(size_t)n * FF + c] + acc + gat_bias[c];
    float s = v, q = v * v;
#pragma unroll
    for (int off = 16; off; off >>= 1) {
        s += __shfl_xor_sync(0xffffffffu, s, off);
        q += __shfl_xor_sync(0xffffffffu, q, off);
    }
    __shared__ float ss[8], sq[8];
    if ((c & 31) == 0) { ss[c >> 5] = s; sq[c >> 5] = q; }
    __syncthreads();
    float S = 0.0f, Q = 0.0f;
#pragma unroll
    for (int i = 0; i < 8; i++) { S += ss[i]; Q += sq[i]; }
    float mu = S * (1.0f / FF);
    float var = Q * (1.0f / FF) - mu * mu;
    g_h[(size_t)n * FF + c] = (v - mu) * rsqrtf(var + 1e-5f) * gam[c] + beta[c];
}

// ---------------- residual + LayerNorm ----------------
__global__ void ln_k(const float* __restrict__ a, const float* __restrict__ b,
                     const float* __restrict__ g, const float* __restrict__ beta,
                     float* __restrict__ o) {
    int n = blockIdx.x, c = threadIdx.x;
    float v = a[(size_t)n * FF + c] + b[(size_t)n * FF + c];
    float s = v, q = v * v;
#pragma unroll
    for (int off = 16; off; off >>= 1) {
        s += __shfl_xor_sync(0xffffffffu, s, off);
        q += __shfl_xor_sync(0xffffffffu, q, off);
    }
    __shared__ float ss[8], sq[8];
    if ((c & 31) == 0) { ss[c >> 5] = s; sq[c >> 5] = q; }
    __syncthreads();
    float S = 0.0f, Q = 0.0f;
#pragma unroll
    for (int i = 0; i < 8; i++) { S += ss[i]; Q += sq[i]; }
    float mu = S * (1.0f / FF);
    float var = Q * (1.0f / FF) - mu * mu;
    o[(size_t)n * FF + c] = (v - mu) * rsqrtf(var + 1e-5f) * g[c] + beta[c];
}

// ---------------- host ----------------
static float* symf(const void* sym) {
    void* p = nullptr;
    cudaGetSymbolAddress(&p, sym);
    return (float*)p;
}

extern "C" void kernel_launch(void* const* d_in, const int* in_sizes, int n_in,
                              void* d_out, int out_size) {
    const float* node_feats  = (const float*)d_in[0];
    const int*   edge_index  = (const int*)d_in[1];
    const float* edge_attr   = (const float*)d_in[2];
    const float* init_node_w = (const float*)d_in[3];
    const float* init_edge_w = (const float*)d_in[4];
    const float* lin_l_w     = (const float*)d_in[5];
    const float* lin_l_b     = (const float*)d_in[6];
    const float* lin_r_w     = (const float*)d_in[7];
    const float* lin_r_b     = (const float*)d_in[8];
    const float* lin_edge_w  = (const float*)d_in[9];
    const float* att         = (const float*)d_in[10];
    const float* gat_bias    = (const float*)d_in[11];
    const float* ln1_g       = (const float*)d_in[12];
    const float* ln1_b       = (const float*)d_in[13];
    const float* mlp_w1      = (const float*)d_in[14];
    const float* mlp_w2      = (const float*)d_in[15];
    const float* ln2_g       = (const float*)d_in[16];
    const float* ln2_b       = (const float*)d_in[17];

    float* px   = symf(g_x);
    float* pxl  = symf(g_xl);
    float* pxr  = symf(g_xr);
    float* ph   = symf(g_h);
    float* py   = symf(g_y);
    float* phid = symf(g_hidden);
    int*   pcnt = (int*)symf(g_cnt_i);

    // x = node_feats @ init_node_w^T
    gemm_nt<0><<<dim3(FF / 64, NN / 128), 256>>>(node_feats, init_node_w, nullptr, px, NN, FF, FIN_NODE);
    // ea (first EE rows) = edge_attr @ init_edge_w^T -> split halves g_eah/g_eal
    gemm_nt<3><<<dim3(FEE / 64, EE / 128), 256>>>(edge_attr, init_edge_w, nullptr, nullptr, EE, FEE, FIN_EDGE);

    // CSR build (edges layer-invariant)
    zeroi<<<(NN + 255) / 256, 256>>>(pcnt, NN);
    csr_count<<<(ET + 255) / 256, 256>>>(edge_index);
    csr_scan<<<1, 256>>>();
    csr_scatter<<<(ET + 255) / 256, 256>>>(edge_index);

    // self-loop attrs
    loop_mean_csr<<<NN, FEE>>>();

    for (int l = 0; l < 2; l++) {
        gemm_dual<<<dim3(8, NN / 128), 256>>>(px,
            lin_l_w + (size_t)l * FF * FF, lin_l_b + l * FF, pxl,
            lin_r_w + (size_t)l * FF * FF, lin_r_b + l * FF, pxr);
        gemm_edge_logit<<<dim3(FF / 128, ET / 128), 256>>>(lin_edge_w + (size_t)l * FF * FEE,
                                                           edge_index, att + l * FF);
        softmax_csr<<<NN / 8, 256>>>();
        aggregate_ln<<<NN, FF>>>(gat_bias + l * FF, ln1_g + l * FF, ln1_b + l * FF);

        gemm_nt<2><<<dim3(512 / 64, NN / 128), 256>>>(ph, mlp_w1 + (size_t)l * 512 * FF,
                                                      nullptr, phid, NN, 512, FF);
        gemm_nt<0><<<dim3(FF / 64, NN / 128), 256>>>(phid, mlp_w2 + (size_t)l * FF * 512,
                                                     nullptr, py, NN, FF, 512);
        float* xo = (l == 1) ? (float*)d_out : px;
        ln_k<<<NN, FF>>>(ph, py, ln2_g + l * FF, ln2_b + l * FF, xo);
    }
}